// round 5
// baseline (speedup 1.0000x reference)
#include <cuda_runtime.h>
#include <math.h>

// AttentionST: two-kernel split, software-pipelined streaming pass.
// K1: t[r]=E[r]·w_att, p[r]=E[r]·w_pred for all B*S rows (double-buffered loads).
// K2: warp-per-b softmax + weighted sum + sigmoid, all register-resident.

constexpr int D = 768;
constexpr int S = 512;
constexpr int MAXROWS = 256 * 512;
constexpr int NT1 = 256;
constexpr int NW1 = NT1 / 32;                 // 8 warps
constexpr int F4_PER_ROW = D / 4;             // 192
constexpr int FL = F4_PER_ROW / 32;           // 6 float4 per lane per row
constexpr int GRID1 = 148;                    // persistent: 1 CTA per SM
constexpr int STRIDE = GRID1 * NW1 * 2;       // 2368 rows per grid step

__device__ float2 g_tp[MAXROWS];              // 1 MB scratch: (t, p) per row

__device__ __forceinline__ void load_rows(
    const float4* __restrict__ E4, int row, int lane,
    float4 v0[FL], float4 v1[FL])
{
    const float4* r0 = E4 + (size_t)row * F4_PER_ROW;
    const float4* r1 = r0 + F4_PER_ROW;
    #pragma unroll
    for (int j = 0; j < FL; j++) v0[j] = r0[j * 32 + lane];
    #pragma unroll
    for (int j = 0; j < FL; j++) v1[j] = r1[j * 32 + lane];
}

__device__ __forceinline__ void compute_store(
    const float4 v0[FL], const float4 v1[FL],
    const float4 wa[FL], const float4 wp[FL],
    int row, int lane)
{
    float t0 = 0.f, p0 = 0.f, t1 = 0.f, p1 = 0.f;
    float t0b = 0.f, p0b = 0.f, t1b = 0.f, p1b = 0.f;
    #pragma unroll
    for (int j = 0; j < FL; j++) {
        t0  = fmaf(v0[j].x, wa[j].x, t0);
        t0b = fmaf(v0[j].y, wa[j].y, t0b);
        t0  = fmaf(v0[j].z, wa[j].z, t0);
        t0b = fmaf(v0[j].w, wa[j].w, t0b);
        p0  = fmaf(v0[j].x, wp[j].x, p0);
        p0b = fmaf(v0[j].y, wp[j].y, p0b);
        p0  = fmaf(v0[j].z, wp[j].z, p0);
        p0b = fmaf(v0[j].w, wp[j].w, p0b);
        t1  = fmaf(v1[j].x, wa[j].x, t1);
        t1b = fmaf(v1[j].y, wa[j].y, t1b);
        t1  = fmaf(v1[j].z, wa[j].z, t1);
        t1b = fmaf(v1[j].w, wa[j].w, t1b);
        p1  = fmaf(v1[j].x, wp[j].x, p1);
        p1b = fmaf(v1[j].y, wp[j].y, p1b);
        p1  = fmaf(v1[j].z, wp[j].z, p1);
        p1b = fmaf(v1[j].w, wp[j].w, p1b);
    }
    t0 += t0b; p0 += p0b; t1 += t1b; p1 += p1b;

    #pragma unroll
    for (int o = 16; o; o >>= 1) {
        t0 += __shfl_xor_sync(0xffffffffu, t0, o);
        p0 += __shfl_xor_sync(0xffffffffu, p0, o);
        t1 += __shfl_xor_sync(0xffffffffu, t1, o);
        p1 += __shfl_xor_sync(0xffffffffu, p1, o);
    }
    if (lane == 0) {
        g_tp[row]     = make_float2(t0, p0);
        g_tp[row + 1] = make_float2(t1, p1);
    }
}

__global__ __launch_bounds__(NT1, 1) void dot_kernel(
    const float* __restrict__ E,
    const float* __restrict__ w_att,
    const float* __restrict__ w_pred,
    int total_rows)
{
    const int warp = threadIdx.x >> 5;
    const int lane = threadIdx.x & 31;

    // Both weight vectors register-resident (48 regs), fixed per lane.
    float4 wa[FL], wp[FL];
    #pragma unroll
    for (int j = 0; j < FL; j++) {
        wa[j] = reinterpret_cast<const float4*>(w_att)[j * 32 + lane];
        wp[j] = reinterpret_cast<const float4*>(w_pred)[j * 32 + lane];
    }

    const float4* E4 = reinterpret_cast<const float4*>(E);
    const int gw = blockIdx.x * NW1 + warp;

    // Software pipeline: buffers A and B ping-pong; next pair's loads are
    // issued before the current pair's compute so this warp always has
    // ~6 KB of LDG.128 in flight.
    float4 a0[FL], a1[FL], b0[FL], b1[FL];
    int row = gw * 2;
    if (row < total_rows) load_rows(E4, row, lane, a0, a1);

    while (row < total_rows) {
        int nrow = row + STRIDE;
        if (nrow < total_rows) load_rows(E4, nrow, lane, b0, b1);
        compute_store(a0, a1, wa, wp, row, lane);
        row = nrow;
        if (row >= total_rows) break;

        nrow = row + STRIDE;
        if (nrow < total_rows) load_rows(E4, nrow, lane, a0, a1);
        compute_store(b0, b1, wa, wp, row, lane);
        row = nrow;
    }
}

// One warp per batch row: 512 float2 -> 32 regs, two shuffle reductions.
__global__ __launch_bounds__(256) void softmax_kernel(
    const float* __restrict__ b_pred,
    float* __restrict__ out,
    int B)
{
    const int warp = threadIdx.x >> 5;
    const int lane = threadIdx.x & 31;
    const int b = blockIdx.x * 8 + warp;
    if (b >= B) return;

    const float2* base = g_tp + (size_t)b * S;
    float2 v[16];
    #pragma unroll
    for (int k = 0; k < 16; k++) v[k] = base[k * 32 + lane];

    float m = -INFINITY;
    #pragma unroll
    for (int k = 0; k < 16; k++) m = fmaxf(m, v[k].x);
    #pragma unroll
    for (int o = 16; o; o >>= 1) m = fmaxf(m, __shfl_xor_sync(0xffffffffu, m, o));

    float se = 0.f, sep = 0.f;
    #pragma unroll
    for (int k = 0; k < 16; k++) {
        float e = __expf(v[k].x - m);
        se += e;
        sep = fmaf(e, v[k].y, sep);
    }
    #pragma unroll
    for (int o = 16; o; o >>= 1) {
        se  += __shfl_xor_sync(0xffffffffu, se, o);
        sep += __shfl_xor_sync(0xffffffffu, sep, o);
    }

    if (lane == 0) {
        float logit = sep / se + b_pred[0];
        out[b] = 1.f / (1.f + __expf(-logit));
    }
}

extern "C" void kernel_launch(void* const* d_in, const int* in_sizes, int n_in,
                              void* d_out, int out_size)
{
    const float* E      = (const float*)d_in[0];
    const float* w_att  = (const float*)d_in[1];
    const float* w_pred = (const float*)d_in[2];
    const float* b_pred = (const float*)d_in[3];
    float* out = (float*)d_out;

    const int B = in_sizes[0] / (S * D);
    const int total_rows = B * S;

    dot_kernel<<<GRID1, NT1>>>(E, w_att, w_pred, total_rows);
    softmax_kernel<<<(B + 7) / 8, 256>>>(b_pred, out, B);
}

// round 6
// speedup vs baseline: 1.0947x; 1.0947x over previous
#include <cuda_runtime.h>
#include <math.h>

// AttentionST: attention pooling, fused single pass (R3 structure, trimmed epilogue).
// E: [B, S, D] fp32, w_att: [D], w_pred: [D], b_pred: scalar -> out: [B]
// logit[b] = sum_s softmax(E[b]·w_att)[s] * (E[b,s]·w_pred) + b_pred; out = sigmoid(logit)

constexpr int D = 768;
constexpr int S = 512;
constexpr int NTHREADS = 256;
constexpr int NWARPS = NTHREADS / 32;
constexpr int F4_PER_ROW = D / 4;             // 192
constexpr int FL = F4_PER_ROW / 32;           // 6 float4 per lane per row

__global__ __launch_bounds__(NTHREADS, 2) void attn_pool_kernel(
    const float* __restrict__ E,
    const float* __restrict__ w_att,
    const float* __restrict__ w_pred,
    const float* __restrict__ b_pred,
    float* __restrict__ out)
{
    __shared__ float2 s_tp[S];        // (score, pred-dot) per position

    const int b    = blockIdx.x;
    const int tid  = threadIdx.x;
    const int warp = tid >> 5;
    const int lane = tid & 31;

    // Both weight vectors register-resident (48 regs), fixed per lane.
    float4 wa[FL], wp[FL];
    #pragma unroll
    for (int j = 0; j < FL; j++) {
        wa[j] = reinterpret_cast<const float4*>(w_att)[j * 32 + lane];
        wp[j] = reinterpret_cast<const float4*>(w_pred)[j * 32 + lane];
    }

    const float4* Eb = reinterpret_cast<const float4*>(E) + (size_t)b * S * F4_PER_ROW;

    // Pass 1: each warp handles 2 adjacent s-rows per iteration.
    // 12 independent LDG.128 (evict-first) in flight; 4 interleaved FMA chains.
    for (int s = 2 * warp; s < S; s += 2 * NWARPS) {
        const float4* r0 = Eb + (size_t)s * F4_PER_ROW;
        const float4* r1 = r0 + F4_PER_ROW;

        float4 v0[FL], v1[FL];
        #pragma unroll
        for (int j = 0; j < FL; j++) v0[j] = __ldcs(r0 + j * 32 + lane);
        #pragma unroll
        for (int j = 0; j < FL; j++) v1[j] = __ldcs(r1 + j * 32 + lane);

        float t0 = 0.f, p0 = 0.f, t1 = 0.f, p1 = 0.f;
        float t0b = 0.f, p0b = 0.f, t1b = 0.f, p1b = 0.f;
        #pragma unroll
        for (int j = 0; j < FL; j++) {
            t0  = fmaf(v0[j].x, wa[j].x, t0);
            t0b = fmaf(v0[j].y, wa[j].y, t0b);
            t0  = fmaf(v0[j].z, wa[j].z, t0);
            t0b = fmaf(v0[j].w, wa[j].w, t0b);
            p0  = fmaf(v0[j].x, wp[j].x, p0);
            p0b = fmaf(v0[j].y, wp[j].y, p0b);
            p0  = fmaf(v0[j].z, wp[j].z, p0);
            p0b = fmaf(v0[j].w, wp[j].w, p0b);
            t1  = fmaf(v1[j].x, wa[j].x, t1);
            t1b = fmaf(v1[j].y, wa[j].y, t1b);
            t1  = fmaf(v1[j].z, wa[j].z, t1);
            t1b = fmaf(v1[j].w, wa[j].w, t1b);
            p1  = fmaf(v1[j].x, wp[j].x, p1);
            p1b = fmaf(v1[j].y, wp[j].y, p1b);
            p1  = fmaf(v1[j].z, wp[j].z, p1);
            p1b = fmaf(v1[j].w, wp[j].w, p1b);
        }
        t0 += t0b; p0 += p0b; t1 += t1b; p1 += p1b;

        #pragma unroll
        for (int o = 16; o; o >>= 1) {
            t0 += __shfl_xor_sync(0xffffffffu, t0, o);
            p0 += __shfl_xor_sync(0xffffffffu, p0, o);
            t1 += __shfl_xor_sync(0xffffffffu, t1, o);
            p1 += __shfl_xor_sync(0xffffffffu, p1, o);
        }
        if (lane == 0) {
            s_tp[s]     = make_float2(t0, p0);
            s_tp[s + 1] = make_float2(t1, p1);
        }
    }
    __syncthreads();

    // Epilogue: warps 1..7 retire immediately; warp 0 does the whole softmax
    // register-resident (16 float2 per lane).
    if (warp != 0) return;

    float2 v[16];
    #pragma unroll
    for (int k = 0; k < 16; k++) v[k] = s_tp[k * 32 + lane];

    float m = -INFINITY;
    #pragma unroll
    for (int k = 0; k < 16; k++) m = fmaxf(m, v[k].x);
    #pragma unroll
    for (int o = 16; o; o >>= 1) m = fmaxf(m, __shfl_xor_sync(0xffffffffu, m, o));

    float se = 0.f, sep = 0.f;
    #pragma unroll
    for (int k = 0; k < 16; k++) {
        float e = __expf(v[k].x - m);
        se += e;
        sep = fmaf(e, v[k].y, sep);
    }
    #pragma unroll
    for (int o = 16; o; o >>= 1) {
        se  += __shfl_xor_sync(0xffffffffu, se, o);
        sep += __shfl_xor_sync(0xffffffffu, sep, o);
    }

    if (lane == 0) {
        float logit = sep / se + b_pred[0];
        out[b] = 1.f / (1.f + __expf(-logit));
    }
}

extern "C" void kernel_launch(void* const* d_in, const int* in_sizes, int n_in,
                              void* d_out, int out_size)
{
    const float* E      = (const float*)d_in[0];
    const float* w_att  = (const float*)d_in[1];
    const float* w_pred = (const float*)d_in[2];
    const float* b_pred = (const float*)d_in[3];
    float* out = (float*)d_out;

    const int B = in_sizes[0] / (S * D);
    attn_pool_kernel<<<B, NTHREADS>>>(E, w_att, w_pred, b_pred, out);
}

// round 7
// speedup vs baseline: 1.1020x; 1.0067x over previous
#include <cuda_runtime.h>
#include <math.h>

// AttentionST: attention pooling, fused single pass.
// E: [B, S, D] fp32, w_att: [D], w_pred: [D], b_pred: scalar -> out: [B]
// logit[b] = sum_s softmax(E[b]·w_att)[s] * (E[b,s]·w_pred) + b_pred; out = sigmoid(logit)
//
// Structure (settled over R1-R6): DRAM-bound at the path-independent ~6.6 TB/s
// chip cap; kernel runs at ~99% of the 402MB/6.64TB/s floor. One CTA per batch
// row, 2 s-rows per warp per iteration (12 LDG.128 in flight), both weight
// vectors register-resident, single barrier, warp-0 register-resident epilogue.

constexpr int D = 768;
constexpr int S = 512;
constexpr int NTHREADS = 256;
constexpr int NWARPS = NTHREADS / 32;
constexpr int F4_PER_ROW = D / 4;             // 192
constexpr int FL = F4_PER_ROW / 32;           // 6 float4 per lane per row

__global__ __launch_bounds__(NTHREADS, 2) void attn_pool_kernel(
    const float* __restrict__ E,
    const float* __restrict__ w_att,
    const float* __restrict__ w_pred,
    const float* __restrict__ b_pred,
    float* __restrict__ out)
{
    __shared__ float2 s_tp[S];        // (score, pred-dot) per position

    const int b    = blockIdx.x;
    const int tid  = threadIdx.x;
    const int warp = tid >> 5;
    const int lane = tid & 31;

    // Prefetch the bias early so its DRAM latency hides under the stream.
    float bias = 0.f;
    if (warp == 0 && lane == 0) bias = b_pred[0];

    // Both weight vectors register-resident (48 regs), fixed per lane.
    float4 wa[FL], wp[FL];
    #pragma unroll
    for (int j = 0; j < FL; j++) {
        wa[j] = reinterpret_cast<const float4*>(w_att)[j * 32 + lane];
        wp[j] = reinterpret_cast<const float4*>(w_pred)[j * 32 + lane];
    }

    const float4* Eb = reinterpret_cast<const float4*>(E) + (size_t)b * S * F4_PER_ROW;

    // Pass 1: each warp handles 2 adjacent s-rows per iteration.
    // 12 independent LDG.128 (evict-first) in flight; 4 interleaved FMA chains.
    for (int s = 2 * warp; s < S; s += 2 * NWARPS) {
        const float4* r0 = Eb + (size_t)s * F4_PER_ROW;
        const float4* r1 = r0 + F4_PER_ROW;

        float4 v0[FL], v1[FL];
        #pragma unroll
        for (int j = 0; j < FL; j++) v0[j] = __ldcs(r0 + j * 32 + lane);
        #pragma unroll
        for (int j = 0; j < FL; j++) v1[j] = __ldcs(r1 + j * 32 + lane);

        float t0 = 0.f, p0 = 0.f, t1 = 0.f, p1 = 0.f;
        float t0b = 0.f, p0b = 0.f, t1b = 0.f, p1b = 0.f;
        #pragma unroll
        for (int j = 0; j < FL; j++) {
            t0  = fmaf(v0[j].x, wa[j].x, t0);
            t0b = fmaf(v0[j].y, wa[j].y, t0b);
            t0  = fmaf(v0[j].z, wa[j].z, t0);
            t0b = fmaf(v0[j].w, wa[j].w, t0b);
            p0  = fmaf(v0[j].x, wp[j].x, p0);
            p0b = fmaf(v0[j].y, wp[j].y, p0b);
            p0  = fmaf(v0[j].z, wp[j].z, p0);
            p0b = fmaf(v0[j].w, wp[j].w, p0b);
            t1  = fmaf(v1[j].x, wa[j].x, t1);
            t1b = fmaf(v1[j].y, wa[j].y, t1b);
            t1  = fmaf(v1[j].z, wa[j].z, t1);
            t1b = fmaf(v1[j].w, wa[j].w, t1b);
            p1  = fmaf(v1[j].x, wp[j].x, p1);
            p1b = fmaf(v1[j].y, wp[j].y, p1b);
            p1  = fmaf(v1[j].z, wp[j].z, p1);
            p1b = fmaf(v1[j].w, wp[j].w, p1b);
        }
        t0 += t0b; p0 += p0b; t1 += t1b; p1 += p1b;

        #pragma unroll
        for (int o = 16; o; o >>= 1) {
            t0 += __shfl_xor_sync(0xffffffffu, t0, o);
            p0 += __shfl_xor_sync(0xffffffffu, p0, o);
            t1 += __shfl_xor_sync(0xffffffffu, t1, o);
            p1 += __shfl_xor_sync(0xffffffffu, p1, o);
        }
        if (lane == 0) {
            // s is even: s_tp[s], s_tp[s+1] are one aligned 16B slot -> STS.128.
            *reinterpret_cast<float4*>(&s_tp[s]) = make_float4(t0, p0, t1, p1);
        }
    }
    __syncthreads();

    // Epilogue: warps 1..7 retire immediately; warp 0 does the whole softmax
    // register-resident (16 float2 per lane).
    if (warp != 0) return;

    float2 v[16];
    #pragma unroll
    for (int k = 0; k < 16; k++) v[k] = s_tp[k * 32 + lane];

    float m = -INFINITY;
    #pragma unroll
    for (int k = 0; k < 16; k++) m = fmaxf(m, v[k].x);
    #pragma unroll
    for (int o = 16; o; o >>= 1) m = fmaxf(m, __shfl_xor_sync(0xffffffffu, m, o));

    float se = 0.f, sep = 0.f;
    #pragma unroll
    for (int k = 0; k < 16; k++) {
        float e = __expf(v[k].x - m);
        se += e;
        sep = fmaf(e, v[k].y, sep);
    }
    #pragma unroll
    for (int o = 16; o; o >>= 1) {
        se  += __shfl_xor_sync(0xffffffffu, se, o);
        sep += __shfl_xor_sync(0xffffffffu, sep, o);
    }

    if (lane == 0) {
        float logit = sep / se + bias;
        out[b] = 1.f / (1.f + __expf(-logit));
    }
}

extern "C" void kernel_launch(void* const* d_in, const int* in_sizes, int n_in,
                              void* d_out, int out_size)
{
    const float* E      = (const float*)d_in[0];
    const float* w_att  = (const float*)d_in[1];
    const float* w_pred = (const float*)d_in[2];
    const float* b_pred = (const float*)d_in[3];
    float* out = (float*)d_out;

    const int B = in_sizes[0] / (S * D);
    attn_pool_kernel<<<B, NTHREADS>>>(E, w_att, w_pred, b_pred, out);
}